// round 14
// baseline (speedup 1.0000x reference)
#include <cuda_runtime.h>
#include <cuda_bf16.h>
#include <math.h>
#include <stdint.h>

constexpr int N_ = 20000;    // nodes; all src/dst values are < N_
constexpr int E_ = 320000;   // edges = line-graph rows

// ---------------- static scratch (allocation-free rule) ----------------
__device__ static float d_xlr_n1[(size_t)N_ * 512];
__device__ static float d_h    [(size_t)N_ * 256];
__device__ static float d_xlr_n2[(size_t)N_ * 128];
__device__ static float d_nr   [(size_t)N_ * 64];
__device__ static float d_xlr_e1[(size_t)N_ * 512];
__device__ static float d_g    [(size_t)N_ * 256];
__device__ static float d_xlr_e2[(size_t)N_ * 128];
__device__ static float d_msg  [N_ * 2];
__device__ static float d_wpr  [256 * 2];
__device__ static float d_cpr  [2];
// concatenated wl|wr weights, n-major [2*Ncol][K], bf16 hi/lo split
__device__ static __nv_bfloat16 d_n1h[512 * 64],  d_n1l[512 * 64];
__device__ static __nv_bfloat16 d_n2h[128 * 256], d_n2l[128 * 256];
__device__ static __nv_bfloat16 d_e1h[512 * 64],  d_e1l[512 * 64];
__device__ static __nv_bfloat16 d_e2h[128 * 256], d_e2l[128 * 256];
__device__ static int   d_cnt[N_];
__device__ static int   d_rowptr[N_ + 1];
__device__ static int   d_headp[N_];
__device__ static int   d_csrs[E_];     // src[j] grouped by dst[j]

// ---------------- streams/events: lazy, capture-safe init ----------------
static cudaStream_t g_s1 = 0, g_s2 = 0;
static cudaEvent_t  g_evA = 0, g_evCSR = 0, g_evF = 0, g_evN = 0, g_evS = 0;
static int g_tried = 0;

static void ensure_resources() {
    if (g_tried) return;
    cudaStreamCaptureStatus st = cudaStreamCaptureStatusNone;
    cudaStreamIsCapturing(0, &st);
    if (st != cudaStreamCaptureStatusNone) return;   // never create mid-capture
    g_tried = 1;
    bool ok = true;
    ok &= (cudaStreamCreateWithFlags(&g_s1, cudaStreamNonBlocking) == cudaSuccess);
    ok &= (cudaStreamCreateWithFlags(&g_s2, cudaStreamNonBlocking) == cudaSuccess);
    ok &= (cudaEventCreateWithFlags(&g_evA,   cudaEventDisableTiming) == cudaSuccess);
    ok &= (cudaEventCreateWithFlags(&g_evCSR, cudaEventDisableTiming) == cudaSuccess);
    ok &= (cudaEventCreateWithFlags(&g_evF,   cudaEventDisableTiming) == cudaSuccess);
    ok &= (cudaEventCreateWithFlags(&g_evN,   cudaEventDisableTiming) == cudaSuccess);
    ok &= (cudaEventCreateWithFlags(&g_evS,   cudaEventDisableTiming) == cudaSuccess);
    if (!ok) { g_s1 = 0; g_s2 = 0; }
}

// ---------------- mma / ldmatrix helpers ----------------
__device__ __forceinline__ void mma_bf16(float* c, const unsigned* a, const unsigned* b) {
    asm volatile(
        "mma.sync.aligned.m16n8k16.row.col.f32.bf16.bf16.f32 "
        "{%0,%1,%2,%3}, {%4,%5,%6,%7}, {%8,%9}, {%0,%1,%2,%3};"
        : "+f"(c[0]), "+f"(c[1]), "+f"(c[2]), "+f"(c[3])
        : "r"(a[0]), "r"(a[1]), "r"(a[2]), "r"(a[3]), "r"(b[0]), "r"(b[1]));
}
__device__ __forceinline__ void ldsm_x4(unsigned* r, unsigned addr) {
    asm volatile("ldmatrix.sync.aligned.m8n8.x4.shared.b16 {%0,%1,%2,%3}, [%4];"
        : "=r"(r[0]), "=r"(r[1]), "=r"(r[2]), "=r"(r[3]) : "r"(addr));
}

// ---------------- helpers ----------------
template<int VEC>
__device__ __forceinline__ void loadv(const float* __restrict__ p, float* r) {
    if constexpr (VEC == 8) {
        float4 a = *(const float4*)p; float4 b = *(const float4*)(p + 4);
        r[0]=a.x; r[1]=a.y; r[2]=a.z; r[3]=a.w; r[4]=b.x; r[5]=b.y; r[6]=b.z; r[7]=b.w;
    } else {
        float2 a = *(const float2*)p; r[0]=a.x; r[1]=a.y;
    }
}
template<int VEC>
__device__ __forceinline__ void storev(float* __restrict__ p, const float* r) {
    if constexpr (VEC == 8) {
        *(float4*)p       = make_float4(r[0], r[1], r[2], r[3]);
        *(float4*)(p + 4) = make_float4(r[4], r[5], r[6], r[7]);
    } else {
        *(float2*)p = make_float2(r[0], r[1]);
    }
}

// ---------------- CSR build ----------------
__global__ void k_hist(const int* __restrict__ dst, int* __restrict__ cnt) {
    int j = blockIdx.x * blockDim.x + threadIdx.x;
    if (j < E_) atomicAdd(&cnt[dst[j]], 1);
}
__global__ void k_scan(const int* __restrict__ cnt, int* __restrict__ rowptr,
                       int* __restrict__ headp) {
    __shared__ int sm[1024];
    const int ITEMS = 20;
    int t = threadIdx.x;
    int base = t * ITEMS;
    int loc[ITEMS];
    int run = 0;
#pragma unroll
    for (int i = 0; i < ITEMS; i++) {
        int idx = base + i;
        int v = (idx < N_) ? cnt[idx] : 0;
        loc[i] = run; run += v;
    }
    sm[t] = run; __syncthreads();
    for (int off = 1; off < 1024; off <<= 1) {
        int v = (t >= off) ? sm[t - off] : 0;
        __syncthreads();
        sm[t] += v;
        __syncthreads();
    }
    int excl = (t == 0) ? 0 : sm[t - 1];
#pragma unroll
    for (int i = 0; i < ITEMS; i++) {
        int idx = base + i;
        if (idx < N_) { int v = excl + loc[i]; rowptr[idx] = v; headp[idx] = v; }
    }
    if (t == 1023) rowptr[N_] = sm[1023];
}
__global__ void k_scatter(const int* __restrict__ src, const int* __restrict__ dst,
                          int* __restrict__ headp, int* __restrict__ csrs) {
    int j = blockIdx.x * blockDim.x + threadIdx.x;
    if (j < E_) {
        int p = atomicAdd(&headp[dst[j]], 1);
        csrs[p] = src[j];
    }
}

// ---------------- merged prolog: wcat x4 + wprime + zero(msg,cnt) ----------------
__device__ __forceinline__ void wcat_one(
    const float* __restrict__ wl, const float* __restrict__ wr,
    int K, int Ncol, int i,
    __nv_bfloat16* __restrict__ oh, __nv_bfloat16* __restrict__ ol)
{
    int n = i / K, k = i - n * K;
    float a = (n < Ncol) ? wl[k * Ncol + n] : wr[k * Ncol + (n - Ncol)];
    __nv_bfloat16 hi = __float2bfloat16(a);
    __nv_bfloat16 lo = __float2bfloat16(a - __bfloat162float(hi));
    oh[i] = hi; ol[i] = lo;
}
// grid: 512 wcat blocks (4 segs x 128) + 157 zero blocks + 1 wprime block
__global__ void k_prolog(
    const float* __restrict__ n1_wl, const float* __restrict__ n1_wr,
    const float* __restrict__ n2_wl, const float* __restrict__ n2_wr,
    const float* __restrict__ e1_wl, const float* __restrict__ e1_wr,
    const float* __restrict__ e2_wl, const float* __restrict__ e2_wr,
    const float* __restrict__ crf_wp, const float* __restrict__ e2_b,
    __nv_bfloat16* __restrict__ n1h, __nv_bfloat16* __restrict__ n1l,
    __nv_bfloat16* __restrict__ n2h, __nv_bfloat16* __restrict__ n2l,
    __nv_bfloat16* __restrict__ e1h, __nv_bfloat16* __restrict__ e1l,
    __nv_bfloat16* __restrict__ e2h, __nv_bfloat16* __restrict__ e2l,
    float* __restrict__ wpr, float* __restrict__ cpr,
    float* __restrict__ msg, int* __restrict__ cnt)
{
    int b = blockIdx.x;
    int t = threadIdx.x;
    if (b < 512) {
        int seg = b >> 7;
        int i = (b & 127) * 256 + t;
        if (seg == 0)      wcat_one(n1_wl, n1_wr, 64, 256, i, n1h, n1l);
        else if (seg == 1) wcat_one(n2_wl, n2_wr, 256, 64, i, n2h, n2l);
        else if (seg == 2) wcat_one(e1_wl, e1_wr, 64, 256, i, e1h, e1l);
        else               wcat_one(e2_wl, e2_wr, 256, 64, i, e2h, e2l);
    } else if (b < 512 + 157) {
        int i = (b - 512) * 256 + t;
        if (i < 2 * N_) msg[i] = 0.f;
        if (i < N_) cnt[i] = 0;
    } else {
        float a0 = 0.f, a1 = 0.f;
#pragma unroll 8
        for (int k = 0; k < 64; k++) {
            float w = e2_wl[t * 64 + k];
            a0 += w * crf_wp[k * 2];
            a1 += w * crf_wp[k * 2 + 1];
        }
        wpr[t * 2] = a0; wpr[t * 2 + 1] = a1;
        if (t < 2) {
            float c = 0.f;
            for (int k = 0; k < 64; k++) c += e2_b[k] * crf_wp[k * 2 + t];
            cpr[t] = c;
        }
    }
}

// ---------------- split-bf16 tensor-core GEMM (dual problem select via blockIdx.z) ----------------
constexpr int ASTR_B = 72;   // bf16 row stride; 144B → ldmatrix conflict-free
constexpr int GEMMT_SMEM = 2 * (128 * ASTR_B * 2) + 2 * (64 * ASTR_B * 2);
__global__ __launch_bounds__(256) void k_gemmt(
    const float* __restrict__ A0, const __nv_bfloat16* __restrict__ Wh0,
    const __nv_bfloat16* __restrict__ Wl0, float* __restrict__ C0,
    const float* __restrict__ A1, const __nv_bfloat16* __restrict__ Wh1,
    const __nv_bfloat16* __restrict__ Wl1, float* __restrict__ C1,
    int M, int K, int Ntot)
{
    const float* A = blockIdx.z ? A1 : A0;
    const __nv_bfloat16* Wh = blockIdx.z ? Wh1 : Wh0;
    const __nv_bfloat16* Wl = blockIdx.z ? Wl1 : Wl0;
    float* C = blockIdx.z ? C1 : C0;

    extern __shared__ __align__(16) char smraw[];
    __nv_bfloat16* Ah  = (__nv_bfloat16*)smraw;          // [128][ASTR_B]
    __nv_bfloat16* Al  = Ah + 128 * ASTR_B;
    __nv_bfloat16* Whs = Al + 128 * ASTR_B;              // [64][ASTR_B]
    __nv_bfloat16* Wls = Whs + 64 * ASTR_B;

    int tid = threadIdx.x;
    int lane = tid & 31, w = tid >> 5;
    int m0w = (w & 1) * 64;
    int n0w = (w >> 1) * 16;
    int row0 = blockIdx.x * 128;
    int col0 = blockIdx.y * 64;

    int lrow = ((lane >> 3) & 1) * 8 + (lane & 7);
    int lcol = (lane >> 4) * 8;
    unsigned ah_base = (unsigned)__cvta_generic_to_shared(
        Ah + (m0w + lrow) * ASTR_B + lcol);
    unsigned al_base = ah_base + 128 * ASTR_B * 2;
    unsigned wh_base = (unsigned)__cvta_generic_to_shared(
        Whs + (n0w + lrow) * ASTR_B + lcol);
    unsigned wl_base = wh_base + 64 * ASTR_B * 2;

    float c[4][2][4];
#pragma unroll
    for (int mt = 0; mt < 4; mt++)
#pragma unroll
        for (int nt = 0; nt < 2; nt++)
#pragma unroll
            for (int f = 0; f < 4; f++) c[mt][nt][f] = 0.f;

    for (int kt = 0; kt < K; kt += 64) {
        __syncthreads();
#pragma unroll
        for (int it = 0; it < 16; it++) {
            int lin = tid + it * 256;
            int r = lin >> 5, c2 = (lin & 31) * 2;
            int gr = row0 + r;
            float2 v = make_float2(0.f, 0.f);
            if (gr < M) v = *(const float2*)(A + (size_t)gr * K + kt + c2);
            __nv_bfloat16 h0 = __float2bfloat16(v.x);
            __nv_bfloat16 l0 = __float2bfloat16(v.x - __bfloat162float(h0));
            __nv_bfloat16 h1 = __float2bfloat16(v.y);
            __nv_bfloat16 l1 = __float2bfloat16(v.y - __bfloat162float(h1));
            *(__nv_bfloat162*)&Ah[r * ASTR_B + c2] = __nv_bfloat162(h0, h1);
            *(__nv_bfloat162*)&Al[r * ASTR_B + c2] = __nv_bfloat162(l0, l1);
        }
#pragma unroll
        for (int it = 0; it < 8; it++) {
            int lin = tid + it * 256;
            int n = lin >> 5, k2 = (lin & 31) * 2;
            *(unsigned*)&Whs[n * ASTR_B + k2] =
                *(const unsigned*)(Wh + (size_t)(col0 + n) * K + kt + k2);
            *(unsigned*)&Wls[n * ASTR_B + k2] =
                *(const unsigned*)(Wl + (size_t)(col0 + n) * K + kt + k2);
        }
        __syncthreads();

#pragma unroll
        for (int ks = 0; ks < 4; ks++) {
            unsigned bh4[4], bl4[4];
            ldsm_x4(bh4, wh_base + ks * 32);
            ldsm_x4(bl4, wl_base + ks * 32);
#pragma unroll
            for (int mt = 0; mt < 4; mt++) {
                unsigned ah[4], al[4];
                ldsm_x4(ah, ah_base + mt * (16 * ASTR_B * 2) + ks * 32);
                ldsm_x4(al, al_base + mt * (16 * ASTR_B * 2) + ks * 32);
#pragma unroll
                for (int nt = 0; nt < 2; nt++) {
                    unsigned bh[2] = { bh4[nt], bh4[nt + 2] };
                    unsigned bl[2] = { bl4[nt], bl4[nt + 2] };
                    mma_bf16(c[mt][nt], ah, bh);
                    mma_bf16(c[mt][nt], ah, bl);
                    mma_bf16(c[mt][nt], al, bh);
                }
            }
        }
    }

#pragma unroll
    for (int mt = 0; mt < 4; mt++) {
        int r = row0 + m0w + mt * 16 + (lane >> 2);
#pragma unroll
        for (int nt = 0; nt < 2; nt++) {
            int col = col0 + n0w + nt * 8 + (lane & 3) * 2;
            if (r < M)
                *(float2*)(C + (size_t)r * Ntot + col) =
                    make_float2(c[mt][nt][0], c[mt][nt][1]);
            if (r + 8 < M)
                *(float2*)(C + (size_t)(r + 8) * Ntot + col) =
                    make_float2(c[mt][nt][2], c[mt][nt][3]);
        }
    }
}

// ---------------- fused empty-row edge path: split-bf16 tensor-core GEMM ----------------
constexpr int FUSED_SMEM_B =
    2 * (128 * ASTR_B * 2) + 2 * (64 * ASTR_B * 2) + (512 + 256 + 256) * 4;
__global__ __launch_bounds__(256) void k_fused(
    const float* __restrict__ A, const float* __restrict__ b1,
    const float* __restrict__ wpr, const float* __restrict__ cpr,
    const __nv_bfloat16* __restrict__ gwh, const __nv_bfloat16* __restrict__ gwl,
    const int* __restrict__ dst, float* __restrict__ msg)
{
    extern __shared__ __align__(16) char smraw[];
    __nv_bfloat16* Ah = (__nv_bfloat16*)smraw;           // [128][ASTR_B]
    __nv_bfloat16* Al = Ah + 128 * ASTR_B;
    __nv_bfloat16* Wh = Al + 128 * ASTR_B;               // [64][ASTR_B]
    __nv_bfloat16* Wl = Wh + 64 * ASTR_B;
    float* Wp   = (float*)(Wl + 64 * ASTR_B);            // [256][2]
    float* Bb   = Wp + 512;                              // [256]
    float* msum = Bb + 256;                              // [128][2]

    int tid = threadIdx.x;
    int lane = tid & 31, w = tid >> 5;
    int m0w = (w & 1) * 64;
    int n0w = (w >> 1) * 16;
    int row0 = N_ + blockIdx.x * 128;

    int lrow = ((lane >> 3) & 1) * 8 + (lane & 7);
    int lcol = (lane >> 4) * 8;
    unsigned ah_base = (unsigned)__cvta_generic_to_shared(
        Ah + (m0w + lrow) * ASTR_B + lcol);
    unsigned al_base = ah_base + 128 * ASTR_B * 2;
    unsigned wh_base = (unsigned)__cvta_generic_to_shared(
        Wh + (n0w + lrow) * ASTR_B + lcol);
    unsigned wl_base = wh_base + 64 * ASTR_B * 2;

    Wp[tid * 2] = wpr[tid * 2]; Wp[tid * 2 + 1] = wpr[tid * 2 + 1];
    Bb[tid] = b1[tid];
    if (tid < 128) { msum[tid * 2] = 0.f; msum[tid * 2 + 1] = 0.f; }

#pragma unroll
    for (int it = 0; it < 16; it++) {
        int lin = tid + it * 256;
        int r = lin >> 5;
        int c = (lin & 31) * 2;
        int gr = row0 + r;
        float2 v = make_float2(0.f, 0.f);
        if (gr < E_) v = *(const float2*)(A + (size_t)gr * 64 + c);
        __nv_bfloat16 h0 = __float2bfloat16(v.x);
        __nv_bfloat16 l0 = __float2bfloat16(v.x - __bfloat162float(h0));
        __nv_bfloat16 h1 = __float2bfloat16(v.y);
        __nv_bfloat16 l1 = __float2bfloat16(v.y - __bfloat162float(h1));
        *(__nv_bfloat162*)&Ah[r * ASTR_B + c] = __nv_bfloat162(h0, h1);
        *(__nv_bfloat162*)&Al[r * ASTR_B + c] = __nv_bfloat162(l0, l1);
    }

    float m0[8], m1[8];
#pragma unroll
    for (int i = 0; i < 8; i++) { m0[i] = 0.f; m1[i] = 0.f; }

    for (int cc = 0; cc < 4; cc++) {
        __syncthreads();
#pragma unroll
        for (int it = 0; it < 8; it++) {
            int lin = tid + it * 256;
            int n = lin >> 5;
            int k2 = (lin & 31) * 2;
            *(unsigned*)&Wh[n * ASTR_B + k2] =
                *(const unsigned*)(gwh + (size_t)(cc * 64 + n) * 64 + k2);
            *(unsigned*)&Wl[n * ASTR_B + k2] =
                *(const unsigned*)(gwl + (size_t)(cc * 64 + n) * 64 + k2);
        }
        __syncthreads();

        float c[4][2][4];
#pragma unroll
        for (int mt = 0; mt < 4; mt++)
#pragma unroll
            for (int nt = 0; nt < 2; nt++)
#pragma unroll
                for (int f = 0; f < 4; f++) c[mt][nt][f] = 0.f;

#pragma unroll
        for (int ks = 0; ks < 4; ks++) {
            unsigned bh4[4], bl4[4];
            ldsm_x4(bh4, wh_base + ks * 32);
            ldsm_x4(bl4, wl_base + ks * 32);
#pragma unroll
            for (int mt = 0; mt < 4; mt++) {
                unsigned ah[4], al[4];
                ldsm_x4(ah, ah_base + mt * (16 * ASTR_B * 2) + ks * 32);
                ldsm_x4(al, al_base + mt * (16 * ASTR_B * 2) + ks * 32);
#pragma unroll
                for (int nt = 0; nt < 2; nt++) {
                    unsigned bh[2] = { bh4[nt], bh4[nt + 2] };
                    unsigned bl[2] = { bl4[nt], bl4[nt + 2] };
                    mma_bf16(c[mt][nt], ah, bh);
                    mma_bf16(c[mt][nt], ah, bl);
                    mma_bf16(c[mt][nt], al, bh);
                }
            }
        }

#pragma unroll
        for (int mt = 0; mt < 4; mt++)
#pragma unroll
            for (int nt = 0; nt < 2; nt++)
#pragma unroll
                for (int f = 0; f < 4; f++) {
                    int col = cc * 64 + n0w + nt * 8 + (lane & 3) * 2 + (f & 1);
                    int mi = mt * 2 + (f >> 1);
                    float v = c[mt][nt][f] + Bb[col];
                    v = v > 0.f ? v : (__expf(v) - 1.f);
                    m0[mi] += v * Wp[col * 2];
                    m1[mi] += v * Wp[col * 2 + 1];
                }
    }

#pragma unroll
    for (int i = 0; i < 8; i++) {
        m0[i] += __shfl_xor_sync(0xffffffffu, m0[i], 1);
        m0[i] += __shfl_xor_sync(0xffffffffu, m0[i], 2);
        m1[i] += __shfl_xor_sync(0xffffffffu, m1[i], 1);
        m1[i] += __shfl_xor_sync(0xffffffffu, m1[i], 2);
    }
    if ((lane & 3) == 0) {
#pragma unroll
        for (int i = 0; i < 8; i++) {
            int r = m0w + (i >> 1) * 16 + (lane >> 2) + (i & 1) * 8;
            atomicAdd(&msum[r * 2],     m0[i]);
            atomicAdd(&msum[r * 2 + 1], m1[i]);
        }
    }
    __syncthreads();
    if (tid < 128) {
        int gr = row0 + tid;
        if (gr < E_) {
            int dn = __ldg(&dst[gr]);
            atomicAdd(&msg[2 * dn],     msum[tid * 2]     + cpr[0]);
            atomicAdd(&msg[2 * dn + 1], msum[tid * 2 + 1] + cpr[1]);
        }
    }
}

// ---------------- fused GATv2 (online segment softmax); dual set via blockIdx.y ----------------
template<int HC>
__global__ __launch_bounds__(256) void k_gat(
    const float* __restrict__ xlr0, const float* __restrict__ att0,
    const float* __restrict__ bias0, float* __restrict__ out0,
    const float* __restrict__ xlr1, const float* __restrict__ att1,
    const float* __restrict__ bias1, float* __restrict__ out1,
    const int* __restrict__ rowptr, const int* __restrict__ csrs,
    int R, int elu)
{
    const float* xlr  = blockIdx.y ? xlr1  : xlr0;
    const float* att  = blockIdx.y ? att1  : att0;
    const float* bias = blockIdx.y ? bias1 : bias0;
    float* out        = blockIdx.y ? out1  : out0;

    constexpr int VEC = HC / 32;
    constexpr int GROUP = 64 / VEC;
    int wid = (int)((blockIdx.x * blockDim.x + threadIdx.x) >> 5);
    int lane = threadIdx.x & 31;
    if (wid >= R) return;

    const float* base = xlr + (size_t)wid * (2 * HC);
    int ch0 = lane * VEC;
    float xl[VEC], xr[VEC], at[VEC], acc[VEC];
    loadv<VEC>(base + ch0, xl);
    loadv<VEC>(base + HC + ch0, xr);
    loadv<VEC>(att + ch0, at);

    float p = 0.f;
#pragma unroll
    for (int i = 0; i < VEC; i++) {
        float v = xl[i] + xr[i];
        v = v > 0.f ? v : 0.2f * v;
        p += at[i] * v;
    }
#pragma unroll
    for (int off = GROUP / 2; off > 0; off >>= 1)
        p += __shfl_xor_sync(0xffffffffu, p, off);

    float m = p, z = 1.f;
#pragma unroll
    for (int i = 0; i < VEC; i++) acc[i] = xl[i];

    int s0 = rowptr[wid], s1 = rowptr[wid + 1];
    for (int q = s0; q < s1; q++) {
        int sv = __ldg(&csrs[q]);
        float xs[VEC];
        loadv<VEC>(xlr + (size_t)sv * (2 * HC) + ch0, xs);
        float pe = 0.f;
#pragma unroll
        for (int i = 0; i < VEC; i++) {
            float v = xs[i] + xr[i];
            v = v > 0.f ? v : 0.2f * v;
            pe += at[i] * v;
        }
#pragma unroll
        for (int off = GROUP / 2; off > 0; off >>= 1)
            pe += __shfl_xor_sync(0xffffffffu, pe, off);

        if (pe <= m) {
            float w = __expf(pe - m);
            z += w;
#pragma unroll
            for (int i = 0; i < VEC; i++) acc[i] += w * xs[i];
        } else {
            float sc = __expf(m - pe);
            z = z * sc + 1.f;
#pragma unroll
            for (int i = 0; i < VEC; i++) acc[i] = acc[i] * sc + xs[i];
            m = pe;
        }
    }
    float inv = 1.f / z;
    float bv[VEC], o[VEC];
    loadv<VEC>(bias + ch0, bv);
#pragma unroll
    for (int i = 0; i < VEC; i++) {
        float v = acc[i] * inv + bv[i];
        if (elu) v = v > 0.f ? v : (__expf(v) - 1.f);
        o[i] = v;
    }
    storev<VEC>(out + (size_t)wid * HC + ch0, o);
}

// ---------------- gat e2 with fused msg projection (HC=64, H=1) ----------------
__global__ __launch_bounds__(256) void k_gat_msg(
    const float* __restrict__ xlr, const float* __restrict__ att,
    const float* __restrict__ bias, const float* __restrict__ wp,
    const int* __restrict__ rowptr, const int* __restrict__ csrs,
    const int* __restrict__ dst, float* __restrict__ msg)
{
    int wid = (int)((blockIdx.x * blockDim.x + threadIdx.x) >> 5);
    int lane = threadIdx.x & 31;
    if (wid >= N_) return;

    const float* base = xlr + (size_t)wid * 128;
    int ch0 = lane * 2;
    float xl[2], xr[2], at[2], acc[2];
    loadv<2>(base + ch0, xl);
    loadv<2>(base + 64 + ch0, xr);
    loadv<2>(att + ch0, at);

    float p = 0.f;
#pragma unroll
    for (int i = 0; i < 2; i++) {
        float v = xl[i] + xr[i];
        v = v > 0.f ? v : 0.2f * v;
        p += at[i] * v;
    }
#pragma unroll
    for (int off = 16; off > 0; off >>= 1)
        p += __shfl_xor_sync(0xffffffffu, p, off);

    float m = p, z = 1.f;
    acc[0] = xl[0]; acc[1] = xl[1];

    int s0 = rowptr[wid], s1 = rowptr[wid + 1];
    for (int q = s0; q < s1; q++) {
        int sv = __ldg(&csrs[q]);
        float xs[2];
        loadv<2>(xlr + (size_t)sv * 128 + ch0, xs);
        float pe = 0.f;
#pragma unroll
        for (int i = 0; i < 2; i++) {
            float v = xs[i] + xr[i];
            v = v > 0.f ? v : 0.2f * v;
            pe += at[i] * v;
        }
#pragma unroll
        for (int off = 16; off > 0; off >>= 1)
            pe += __shfl_xor_sync(0xffffffffu, pe, off);

        if (pe <= m) {
            float w = __expf(pe - m);
            z += w;
            acc[0] += w * xs[0]; acc[1] += w * xs[1];
        } else {
            float sc = __expf(m - pe);
            z = z * sc + 1.f;
            acc[0] = acc[0] * sc + xs[0]; acc[1] = acc[1] * sc + xs[1];
            m = pe;
        }
    }
    float inv = 1.f / z;
    float o0 = acc[0] * inv + bias[ch0];
    float o1 = acc[1] * inv + bias[ch0 + 1];
    float pm0 = o0 * wp[ch0 * 2]     + o1 * wp[(ch0 + 1) * 2];
    float pm1 = o0 * wp[ch0 * 2 + 1] + o1 * wp[(ch0 + 1) * 2 + 1];
#pragma unroll
    for (int off = 16; off > 0; off >>= 1) {
        pm0 += __shfl_xor_sync(0xffffffffu, pm0, off);
        pm1 += __shfl_xor_sync(0xffffffffu, pm1, off);
    }
    if (lane == 0) {
        int dn = __ldg(&dst[wid]);
        atomicAdd(&msg[2 * dn],     pm0);
        atomicAdd(&msg[2 * dn + 1], pm1);
    }
}

// ---------------- CRF + proxy heads ----------------
__global__ __launch_bounds__(256) void k_head(
    const float* __restrict__ nr, const float* __restrict__ msg,
    const float* __restrict__ wu, const float* __restrict__ bu,
    const float* __restrict__ w1, const float* __restrict__ b1,
    const float* __restrict__ w2, const float* __restrict__ b2,
    float* __restrict__ out)
{
    __shared__ float s_w1[64 * 128];
    __shared__ float s_w2[128 * 2];
    __shared__ float s_wu[128];
    int tid = threadIdx.x;
    for (int i = tid; i < 64 * 128; i += 256) s_w1[i] = w1[i];
    if (tid < 256) s_w2[tid] = w2[tid];
    if (tid < 128) s_wu[tid] = wu[tid];
    __syncthreads();

    int wid = (int)((blockIdx.x * blockDim.x + tid) >> 5);
    int lane = tid & 31;
    if (wid >= N_) return;

    int k0 = lane * 2;
    float2 xp = *(const float2*)(nr + (size_t)wid * 64 + k0);
    float x0 = xp.x, x1 = xp.y;

    float u0 = x0 * s_wu[k0 * 2]     + x1 * s_wu[(k0 + 1) * 2];
    float u1 = x0 * s_wu[k0 * 2 + 1] + x1 * s_wu[(k0 + 1) * 2 + 1];
#pragma unroll
    for (int off = 16; off > 0; off >>= 1) {
        u0 += __shfl_xor_sync(0xffffffffu, u0, off);
        u1 += __shfl_xor_sync(0xffffffffu, u1, off);
    }
    float v0 = u0 + bu[0] + msg[2 * wid];
    float v1 = u1 + bu[1] + msg[2 * wid + 1];
    float mx = fmaxf(v0, v1);
    float l = logf(__expf(v0 - mx) + __expf(v1 - mx));

    int c0 = lane * 4;
    float ph[4];
#pragma unroll
    for (int jj = 0; jj < 4; jj++) ph[jj] = b1[c0 + jj];
    for (int k = 0; k < 64; k++) {
        float xk = __shfl_sync(0xffffffffu, (k & 1) ? x1 : x0, k >> 1);
#pragma unroll
        for (int jj = 0; jj < 4; jj++) ph[jj] += xk * s_w1[k * 128 + c0 + jj];
    }
    float p0 = 0.f, p1 = 0.f;
#pragma unroll
    for (int jj = 0; jj < 4; jj++) {
        float r = ph[jj] > 0.f ? ph[jj] : 0.f;
        p0 += r * s_w2[(c0 + jj) * 2];
        p1 += r * s_w2[(c0 + jj) * 2 + 1];
    }
#pragma unroll
    for (int off = 16; off > 0; off >>= 1) {
        p0 += __shfl_xor_sync(0xffffffffu, p0, off);
        p1 += __shfl_xor_sync(0xffffffffu, p1, off);
    }
    if (lane == 0) {
        out[(size_t)wid * 2]     = v0 - mx - l;
        out[(size_t)wid * 2 + 1] = v1 - mx - l;
        out[(size_t)2 * N_ + wid * 2]     = p0 + b2[0];
        out[(size_t)2 * N_ + wid * 2 + 1] = p1 + b2[1];
    }
}

// ---------------- launch ----------------
extern "C" void kernel_launch(void* const* d_in, const int* in_sizes, int n_in,
                              void* d_out, int out_size)
{
    const float* x         = (const float*)d_in[0];
    const float* edge_type = (const float*)d_in[1];
    const int*   ei        = (const int*)  d_in[2];
    const float* n1_wl = (const float*)d_in[3];
    const float* n1_wr = (const float*)d_in[4];
    const float* n1_att= (const float*)d_in[5];
    const float* n1_b  = (const float*)d_in[6];
    const float* n2_wl = (const float*)d_in[7];
    const float* n2_wr = (const float*)d_in[8];
    const float* n2_att= (const float*)d_in[9];
    const float* n2_b  = (const float*)d_in[10];
    const float* e1_wl = (const float*)d_in[11];
    const float* e1_wr = (const float*)d_in[12];
    const float* e1_att= (const float*)d_in[13];
    const float* e1_b  = (const float*)d_in[14];
    const float* e2_wl = (const float*)d_in[15];
    const float* e2_wr = (const float*)d_in[16];
    const float* e2_att= (const float*)d_in[17];
    const float* e2_b  = (const float*)d_in[18];
    const float* crf_wu= (const float*)d_in[19];
    const float* crf_bu= (const float*)d_in[20];
    const float* crf_wp= (const float*)d_in[21];
    const float* px_w1 = (const float*)d_in[22];
    const float* px_b1 = (const float*)d_in[23];
    const float* px_w2 = (const float*)d_in[24];
    const float* px_b2 = (const float*)d_in[25];

    const int* src = ei;
    const int* dst = ei + E_;

    float *xlr_n1, *h, *xlr_n2, *nr, *xlr_e1, *g, *xlr_e2, *msg, *wpr, *cpr;
    __nv_bfloat16 *n1h, *n1l, *n2h, *n2l, *e1h, *e1l, *e2h, *e2l;
    int *cnt, *rowptr, *headp, *csrs;
    cudaGetSymbolAddress((void**)&xlr_n1, d_xlr_n1);
    cudaGetSymbolAddress((void**)&h,      d_h);
    cudaGetSymbolAddress((void**)&xlr_n2, d_xlr_n2);
    cudaGetSymbolAddress((void**)&nr,     d_nr);
    cudaGetSymbolAddress((void**)&xlr_e1, d_xlr_e1);
    cudaGetSymbolAddress((void**)&g,      d_g);
    cudaGetSymbolAddress((void**)&xlr_e2, d_xlr_e2);
    cudaGetSymbolAddress((void**)&msg,    d_msg);
    cudaGetSymbolAddress((void**)&wpr,    d_wpr);
    cudaGetSymbolAddress((void**)&cpr,    d_cpr);
    cudaGetSymbolAddress((void**)&n1h,    d_n1h);
    cudaGetSymbolAddress((void**)&n1l,    d_n1l);
    cudaGetSymbolAddress((void**)&n2h,    d_n2h);
    cudaGetSymbolAddress((void**)&n2l,    d_n2l);
    cudaGetSymbolAddress((void**)&e1h,    d_e1h);
    cudaGetSymbolAddress((void**)&e1l,    d_e1l);
    cudaGetSymbolAddress((void**)&e2h,    d_e2h);
    cudaGetSymbolAddress((void**)&e2l,    d_e2l);
    cudaGetSymbolAddress((void**)&cnt,    d_cnt);
    cudaGetSymbolAddress((void**)&rowptr, d_rowptr);
    cudaGetSymbolAddress((void**)&headp,  d_headp);
    cudaGetSymbolAddress((void**)&csrs,   d_csrs);

    cudaFuncSetAttribute(k_fused, cudaFuncAttributeMaxDynamicSharedMemorySize,
                         FUSED_SMEM_B);
    cudaFuncSetAttribute(k_gemmt, cudaFuncAttributeMaxDynamicSharedMemorySize,
                         GEMMT_SMEM);

    const int GB_N = (N_ + 127) / 128;             // 157
    const int GW_N = (N_ + 7) / 8;                 // 2500
    const int FUSED_BLKS = (E_ - N_ + 127) / 128;  // 2344

    ensure_resources();
    const bool forked = (g_s1 != 0 && g_s2 != 0);

    // ---- merged prolog ----
    k_prolog<<<512 + 157 + 1, 256>>>(n1_wl, n1_wr, n2_wl, n2_wr,
                                     e1_wl, e1_wr, e2_wl, e2_wr,
                                     crf_wp, e2_b,
                                     n1h, n1l, n2h, n2l, e1h, e1l, e2h, e2l,
                                     wpr, cpr, msg, cnt);

    if (forked) {
        cudaEventRecord(g_evA, 0);
        cudaStreamWaitEvent(g_s1, g_evA, 0);
        cudaStreamWaitEvent(g_s2, g_evA, 0);

        // s2: BOTH layer-1 GEMMs (node + edge) in one launch — critical chain first
        k_gemmt<<<dim3(GB_N, 8, 2), 256, GEMMT_SMEM, g_s2>>>(
            x, n1h, n1l, xlr_n1, edge_type, e1h, e1l, xlr_e1, N_, 64, 512);

        // s1: fused empty-row edge path
        k_fused<<<FUSED_BLKS, 256, FUSED_SMEM_B, g_s1>>>(edge_type, e1_b, wpr, cpr,
                                                         e1h, e1l, dst, msg);
        cudaEventRecord(g_evF, g_s1);

        // s0: CSR build (concurrent with gemmt + fused)
        k_hist   <<<(E_ + 255) / 256, 256>>>(dst, cnt);
        k_scan   <<<1, 1024>>>(cnt, rowptr, headp);
        k_scatter<<<(E_ + 255) / 256, 256>>>(src, dst, headp, csrs);
        cudaEventRecord(g_evCSR, 0);
        cudaStreamWaitEvent(g_s2, g_evCSR, 0);

        // s2: BOTH gat<256> (node h, edge g)
        k_gat<256><<<dim3(GW_N, 2), 256, 0, g_s2>>>(
            xlr_n1, n1_att, n1_b, h, xlr_e1, e1_att, e1_b, g,
            rowptr, csrs, N_, 1);
        // s2: BOTH layer-2 GEMMs
        k_gemmt<<<dim3(GB_N, 2, 2), 256, GEMMT_SMEM, g_s2>>>(
            h, n2h, n2l, xlr_n2, g, e2h, e2l, xlr_e2, N_, 256, 128);
        cudaEventRecord(g_evS, g_s2);
        cudaStreamWaitEvent(0, g_evS, 0);

        // s2: node gat<64> -> nr;  s0: edge gat_msg -> msg (independent)
        k_gat<64><<<dim3(GW_N, 1), 256, 0, g_s2>>>(
            xlr_n2, n2_att, n2_b, nr, xlr_n2, n2_att, n2_b, nr,
            rowptr, csrs, N_, 0);
        cudaEventRecord(g_evN, g_s2);
        k_gat_msg<<<GW_N, 256>>>(xlr_e2, e2_att, e2_b, crf_wp, rowptr, csrs, dst, msg);

        // join + heads (s0: after gat_msg in-order; wait nr + fused msg)
        cudaStreamWaitEvent(0, g_evF, 0);
        cudaStreamWaitEvent(0, g_evN, 0);
        k_head<<<GW_N, 256>>>(nr, msg, crf_wu, crf_bu, px_w1, px_b1, px_w2, px_b2,
                              (float*)d_out);
    } else {
        // serial fallback (same work, single stream)
        k_fused<<<FUSED_BLKS, 256, FUSED_SMEM_B>>>(edge_type, e1_b, wpr, cpr,
                                                   e1h, e1l, dst, msg);

        k_hist   <<<(E_ + 255) / 256, 256>>>(dst, cnt);
        k_scan   <<<1, 1024>>>(cnt, rowptr, headp);
        k_scatter<<<(E_ + 255) / 256, 256>>>(src, dst, headp, csrs);

        k_gemmt<<<dim3(GB_N, 8, 2), 256, GEMMT_SMEM>>>(
            x, n1h, n1l, xlr_n1, edge_type, e1h, e1l, xlr_e1, N_, 64, 512);
        k_gat<256><<<dim3(GW_N, 2), 256>>>(
            xlr_n1, n1_att, n1_b, h, xlr_e1, e1_att, e1_b, g,
            rowptr, csrs, N_, 1);
        k_gemmt<<<dim3(GB_N, 2, 2), 256, GEMMT_SMEM>>>(
            h, n2h, n2l, xlr_n2, g, e2h, e2l, xlr_e2, N_, 256, 128);
        k_gat<64><<<dim3(GW_N, 1), 256>>>(
            xlr_n2, n2_att, n2_b, nr, xlr_n2, n2_att, n2_b, nr,
            rowptr, csrs, N_, 0);
        k_gat_msg<<<GW_N, 256>>>(xlr_e2, e2_att, e2_b, crf_wp, rowptr, csrs, dst, msg);

        k_head<<<GW_N, 256>>>(nr, msg, crf_wu, crf_bu, px_w1, px_b1, px_w2, px_b2,
                              (float*)d_out);
    }
}

// round 17
// speedup vs baseline: 1.0095x; 1.0095x over previous
#include <cuda_runtime.h>
#include <cuda_bf16.h>
#include <math.h>
#include <stdint.h>

constexpr int N_ = 20000;    // nodes; all src/dst values are < N_
constexpr int E_ = 320000;   // edges = line-graph rows

// ---------------- static scratch (allocation-free rule) ----------------
__device__ static float d_xlr_n1[(size_t)N_ * 512];
__device__ static float d_h    [(size_t)N_ * 256];
__device__ static float d_xlr_n2[(size_t)N_ * 128];
__device__ static float d_nr   [(size_t)N_ * 64];
__device__ static float d_xlr_e1[(size_t)N_ * 512];
__device__ static float d_g    [(size_t)N_ * 256];
__device__ static float d_xlr_e2[(size_t)N_ * 128];
__device__ static float d_msg  [N_ * 2];
__device__ static float d_wpr  [256 * 2];
__device__ static float d_cpr  [2];
// concatenated wl|wr weights, n-major [2*Ncol][K], bf16 hi/lo split
__device__ static __nv_bfloat16 d_n1h[512 * 64],  d_n1l[512 * 64];
__device__ static __nv_bfloat16 d_n2h[128 * 256], d_n2l[128 * 256];
__device__ static __nv_bfloat16 d_e1h[512 * 64],  d_e1l[512 * 64];
__device__ static __nv_bfloat16 d_e2h[128 * 256], d_e2l[128 * 256];
__device__ static int   d_cnt[N_];
__device__ static int   d_rowptr[N_ + 1];
__device__ static int   d_headp[N_];
__device__ static int   d_csrs[E_];     // src[j] grouped by dst[j]

// ---------------- streams/events: lazy, capture-safe init ----------------
static cudaStream_t g_s1 = 0, g_s2 = 0;
static cudaEvent_t  g_evA = 0, g_evCSR = 0, g_evF = 0, g_evN = 0, g_evS = 0;
static int g_tried = 0;

static void ensure_resources() {
    if (g_tried) return;
    cudaStreamCaptureStatus st = cudaStreamCaptureStatusNone;
    cudaStreamIsCapturing(0, &st);
    if (st != cudaStreamCaptureStatusNone) return;   // never create mid-capture
    g_tried = 1;
    bool ok = true;
    ok &= (cudaStreamCreateWithFlags(&g_s1, cudaStreamNonBlocking) == cudaSuccess);
    ok &= (cudaStreamCreateWithFlags(&g_s2, cudaStreamNonBlocking) == cudaSuccess);
    ok &= (cudaEventCreateWithFlags(&g_evA,   cudaEventDisableTiming) == cudaSuccess);
    ok &= (cudaEventCreateWithFlags(&g_evCSR, cudaEventDisableTiming) == cudaSuccess);
    ok &= (cudaEventCreateWithFlags(&g_evF,   cudaEventDisableTiming) == cudaSuccess);
    ok &= (cudaEventCreateWithFlags(&g_evN,   cudaEventDisableTiming) == cudaSuccess);
    ok &= (cudaEventCreateWithFlags(&g_evS,   cudaEventDisableTiming) == cudaSuccess);
    if (!ok) { g_s1 = 0; g_s2 = 0; }
}

// ---------------- mma / ldmatrix helpers ----------------
__device__ __forceinline__ void mma_bf16(float* c, const unsigned* a, const unsigned* b) {
    asm volatile(
        "mma.sync.aligned.m16n8k16.row.col.f32.bf16.bf16.f32 "
        "{%0,%1,%2,%3}, {%4,%5,%6,%7}, {%8,%9}, {%0,%1,%2,%3};"
        : "+f"(c[0]), "+f"(c[1]), "+f"(c[2]), "+f"(c[3])
        : "r"(a[0]), "r"(a[1]), "r"(a[2]), "r"(a[3]), "r"(b[0]), "r"(b[1]));
}
__device__ __forceinline__ void ldsm_x4(unsigned* r, unsigned addr) {
    asm volatile("ldmatrix.sync.aligned.m8n8.x4.shared.b16 {%0,%1,%2,%3}, [%4];"
        : "=r"(r[0]), "=r"(r[1]), "=r"(r[2]), "=r"(r[3]) : "r"(addr));
}

// ---------------- helpers ----------------
template<int VEC>
__device__ __forceinline__ void loadv(const float* __restrict__ p, float* r) {
    if constexpr (VEC == 8) {
        float4 a = *(const float4*)p; float4 b = *(const float4*)(p + 4);
        r[0]=a.x; r[1]=a.y; r[2]=a.z; r[3]=a.w; r[4]=b.x; r[5]=b.y; r[6]=b.z; r[7]=b.w;
    } else {
        float2 a = *(const float2*)p; r[0]=a.x; r[1]=a.y;
    }
}
template<int VEC>
__device__ __forceinline__ void storev(float* __restrict__ p, const float* r) {
    if constexpr (VEC == 8) {
        *(float4*)p       = make_float4(r[0], r[1], r[2], r[3]);
        *(float4*)(p + 4) = make_float4(r[4], r[5], r[6], r[7]);
    } else {
        *(float2*)p = make_float2(r[0], r[1]);
    }
}

// ---------------- CSR build ----------------
__global__ void k_hist(const int* __restrict__ dst, int* __restrict__ cnt) {
    int j = blockIdx.x * blockDim.x + threadIdx.x;
    if (j < E_) atomicAdd(&cnt[dst[j]], 1);
}
__global__ void k_scan(const int* __restrict__ cnt, int* __restrict__ rowptr,
                       int* __restrict__ headp) {
    __shared__ int sm[1024];
    const int ITEMS = 20;
    int t = threadIdx.x;
    int base = t * ITEMS;
    int loc[ITEMS];
    int run = 0;
#pragma unroll
    for (int i = 0; i < ITEMS; i++) {
        int idx = base + i;
        int v = (idx < N_) ? cnt[idx] : 0;
        loc[i] = run; run += v;
    }
    sm[t] = run; __syncthreads();
    for (int off = 1; off < 1024; off <<= 1) {
        int v = (t >= off) ? sm[t - off] : 0;
        __syncthreads();
        sm[t] += v;
        __syncthreads();
    }
    int excl = (t == 0) ? 0 : sm[t - 1];
#pragma unroll
    for (int i = 0; i < ITEMS; i++) {
        int idx = base + i;
        if (idx < N_) { int v = excl + loc[i]; rowptr[idx] = v; headp[idx] = v; }
    }
    if (t == 1023) rowptr[N_] = sm[1023];
}
__global__ void k_scatter(const int* __restrict__ src, const int* __restrict__ dst,
                          int* __restrict__ headp, int* __restrict__ csrs) {
    int j = blockIdx.x * blockDim.x + threadIdx.x;
    if (j < E_) {
        int p = atomicAdd(&headp[dst[j]], 1);
        csrs[p] = src[j];
    }
}

// ---------------- merged prolog: wcat x4 + wprime + zero(msg,cnt) ----------------
__device__ __forceinline__ void wcat_one(
    const float* __restrict__ wl, const float* __restrict__ wr,
    int K, int Ncol, int i,
    __nv_bfloat16* __restrict__ oh, __nv_bfloat16* __restrict__ ol)
{
    int n = i / K, k = i - n * K;
    float a = (n < Ncol) ? wl[k * Ncol + n] : wr[k * Ncol + (n - Ncol)];
    __nv_bfloat16 hi = __float2bfloat16(a);
    __nv_bfloat16 lo = __float2bfloat16(a - __bfloat162float(hi));
    oh[i] = hi; ol[i] = lo;
}
// grid: 512 wcat blocks (4 segs x 128) + 157 zero blocks + 1 wprime block
__global__ void k_prolog(
    const float* __restrict__ n1_wl, const float* __restrict__ n1_wr,
    const float* __restrict__ n2_wl, const float* __restrict__ n2_wr,
    const float* __restrict__ e1_wl, const float* __restrict__ e1_wr,
    const float* __restrict__ e2_wl, const float* __restrict__ e2_wr,
    const float* __restrict__ crf_wp, const float* __restrict__ e2_b,
    __nv_bfloat16* __restrict__ n1h, __nv_bfloat16* __restrict__ n1l,
    __nv_bfloat16* __restrict__ n2h, __nv_bfloat16* __restrict__ n2l,
    __nv_bfloat16* __restrict__ e1h, __nv_bfloat16* __restrict__ e1l,
    __nv_bfloat16* __restrict__ e2h, __nv_bfloat16* __restrict__ e2l,
    float* __restrict__ wpr, float* __restrict__ cpr,
    float* __restrict__ msg, int* __restrict__ cnt)
{
    int b = blockIdx.x;
    int t = threadIdx.x;
    if (b < 512) {
        int seg = b >> 7;
        int i = (b & 127) * 256 + t;
        if (seg == 0)      wcat_one(n1_wl, n1_wr, 64, 256, i, n1h, n1l);
        else if (seg == 1) wcat_one(n2_wl, n2_wr, 256, 64, i, n2h, n2l);
        else if (seg == 2) wcat_one(e1_wl, e1_wr, 64, 256, i, e1h, e1l);
        else               wcat_one(e2_wl, e2_wr, 256, 64, i, e2h, e2l);
    } else if (b < 512 + 157) {
        int i = (b - 512) * 256 + t;
        if (i < 2 * N_) msg[i] = 0.f;
        if (i < N_) cnt[i] = 0;
    } else {
        float a0 = 0.f, a1 = 0.f;
#pragma unroll 8
        for (int k = 0; k < 64; k++) {
            float w = e2_wl[t * 64 + k];
            a0 += w * crf_wp[k * 2];
            a1 += w * crf_wp[k * 2 + 1];
        }
        wpr[t * 2] = a0; wpr[t * 2 + 1] = a1;
        if (t < 2) {
            float c = 0.f;
            for (int k = 0; k < 64; k++) c += e2_b[k] * crf_wp[k * 2 + t];
            cpr[t] = c;
        }
    }
}

// ---------------- split-bf16 tensor-core GEMM (dual problem select via blockIdx.z) ----------------
constexpr int ASTR_B = 72;   // bf16 row stride; 144B → ldmatrix conflict-free
constexpr int GEMMT_SMEM = 2 * (128 * ASTR_B * 2) + 2 * (64 * ASTR_B * 2);
__global__ __launch_bounds__(256) void k_gemmt(
    const float* __restrict__ A0, const __nv_bfloat16* __restrict__ Wh0,
    const __nv_bfloat16* __restrict__ Wl0, float* __restrict__ C0,
    const float* __restrict__ A1, const __nv_bfloat16* __restrict__ Wh1,
    const __nv_bfloat16* __restrict__ Wl1, float* __restrict__ C1,
    int M, int K, int Ntot)
{
    const float* A = blockIdx.z ? A1 : A0;
    const __nv_bfloat16* Wh = blockIdx.z ? Wh1 : Wh0;
    const __nv_bfloat16* Wl = blockIdx.z ? Wl1 : Wl0;
    float* C = blockIdx.z ? C1 : C0;

    extern __shared__ __align__(16) char smraw[];
    __nv_bfloat16* Ah  = (__nv_bfloat16*)smraw;          // [128][ASTR_B]
    __nv_bfloat16* Al  = Ah + 128 * ASTR_B;
    __nv_bfloat16* Whs = Al + 128 * ASTR_B;              // [64][ASTR_B]
    __nv_bfloat16* Wls = Whs + 64 * ASTR_B;

    int tid = threadIdx.x;
    int lane = tid & 31, w = tid >> 5;
    int m0w = (w & 1) * 64;
    int n0w = (w >> 1) * 16;
    int row0 = blockIdx.x * 128;
    int col0 = blockIdx.y * 64;

    int lrow = ((lane >> 3) & 1) * 8 + (lane & 7);
    int lcol = (lane >> 4) * 8;
    unsigned ah_base = (unsigned)__cvta_generic_to_shared(
        Ah + (m0w + lrow) * ASTR_B + lcol);
    unsigned al_base = ah_base + 128 * ASTR_B * 2;
    unsigned wh_base = (unsigned)__cvta_generic_to_shared(
        Whs + (n0w + lrow) * ASTR_B + lcol);
    unsigned wl_base = wh_base + 64 * ASTR_B * 2;

    float c[4][2][4];
#pragma unroll
    for (int mt = 0; mt < 4; mt++)
#pragma unroll
        for (int nt = 0; nt < 2; nt++)
#pragma unroll
            for (int f = 0; f < 4; f++) c[mt][nt][f] = 0.f;

    for (int kt = 0; kt < K; kt += 64) {
        __syncthreads();
#pragma unroll
        for (int it = 0; it < 16; it++) {
            int lin = tid + it * 256;
            int r = lin >> 5, c2 = (lin & 31) * 2;
            int gr = row0 + r;
            float2 v = make_float2(0.f, 0.f);
            if (gr < M) v = *(const float2*)(A + (size_t)gr * K + kt + c2);
            __nv_bfloat16 h0 = __float2bfloat16(v.x);
            __nv_bfloat16 l0 = __float2bfloat16(v.x - __bfloat162float(h0));
            __nv_bfloat16 h1 = __float2bfloat16(v.y);
            __nv_bfloat16 l1 = __float2bfloat16(v.y - __bfloat162float(h1));
            *(__nv_bfloat162*)&Ah[r * ASTR_B + c2] = __nv_bfloat162(h0, h1);
            *(__nv_bfloat162*)&Al[r * ASTR_B + c2] = __nv_bfloat162(l0, l1);
        }
#pragma unroll
        for (int it = 0; it < 8; it++) {
            int lin = tid + it * 256;
            int n = lin >> 5, k2 = (lin & 31) * 2;
            *(unsigned*)&Whs[n * ASTR_B + k2] =
                *(const unsigned*)(Wh + (size_t)(col0 + n) * K + kt + k2);
            *(unsigned*)&Wls[n * ASTR_B + k2] =
                *(const unsigned*)(Wl + (size_t)(col0 + n) * K + kt + k2);
        }
        __syncthreads();

#pragma unroll
        for (int ks = 0; ks < 4; ks++) {
            unsigned bh4[4], bl4[4];
            ldsm_x4(bh4, wh_base + ks * 32);
            ldsm_x4(bl4, wl_base + ks * 32);
#pragma unroll
            for (int mt = 0; mt < 4; mt++) {
                unsigned ah[4], al[4];
                ldsm_x4(ah, ah_base + mt * (16 * ASTR_B * 2) + ks * 32);
                ldsm_x4(al, al_base + mt * (16 * ASTR_B * 2) + ks * 32);
#pragma unroll
                for (int nt = 0; nt < 2; nt++) {
                    unsigned bh[2] = { bh4[nt], bh4[nt + 2] };
                    unsigned bl[2] = { bl4[nt], bl4[nt + 2] };
                    mma_bf16(c[mt][nt], ah, bh);
                    mma_bf16(c[mt][nt], ah, bl);
                    mma_bf16(c[mt][nt], al, bh);
                }
            }
        }
    }

#pragma unroll
    for (int mt = 0; mt < 4; mt++) {
        int r = row0 + m0w + mt * 16 + (lane >> 2);
#pragma unroll
        for (int nt = 0; nt < 2; nt++) {
            int col = col0 + n0w + nt * 8 + (lane & 3) * 2;
            if (r < M)
                *(float2*)(C + (size_t)r * Ntot + col) =
                    make_float2(c[mt][nt][0], c[mt][nt][1]);
            if (r + 8 < M)
                *(float2*)(C + (size_t)(r + 8) * Ntot + col) =
                    make_float2(c[mt][nt][2], c[mt][nt][3]);
        }
    }
}

// ---------------- fused empty-row edge path: split-bf16 tensor-core GEMM ----------------
constexpr int FUSED_SMEM_B =
    2 * (128 * ASTR_B * 2) + 2 * (64 * ASTR_B * 2) + (512 + 256 + 256) * 4;
__global__ __launch_bounds__(256) void k_fused(
    const float* __restrict__ A, const float* __restrict__ b1,
    const float* __restrict__ wpr, const float* __restrict__ cpr,
    const __nv_bfloat16* __restrict__ gwh, const __nv_bfloat16* __restrict__ gwl,
    const int* __restrict__ dst, float* __restrict__ msg)
{
    extern __shared__ __align__(16) char smraw[];
    __nv_bfloat16* Ah = (__nv_bfloat16*)smraw;           // [128][ASTR_B]
    __nv_bfloat16* Al = Ah + 128 * ASTR_B;
    __nv_bfloat16* Wh = Al + 128 * ASTR_B;               // [64][ASTR_B]
    __nv_bfloat16* Wl = Wh + 64 * ASTR_B;
    float* Wp   = (float*)(Wl + 64 * ASTR_B);            // [256][2]
    float* Bb   = Wp + 512;                              // [256]
    float* msum = Bb + 256;                              // [128][2]

    int tid = threadIdx.x;
    int lane = tid & 31, w = tid >> 5;
    int m0w = (w & 1) * 64;
    int n0w = (w >> 1) * 16;
    int row0 = N_ + blockIdx.x * 128;

    int lrow = ((lane >> 3) & 1) * 8 + (lane & 7);
    int lcol = (lane >> 4) * 8;
    unsigned ah_base = (unsigned)__cvta_generic_to_shared(
        Ah + (m0w + lrow) * ASTR_B + lcol);
    unsigned al_base = ah_base + 128 * ASTR_B * 2;
    unsigned wh_base = (unsigned)__cvta_generic_to_shared(
        Wh + (n0w + lrow) * ASTR_B + lcol);
    unsigned wl_base = wh_base + 64 * ASTR_B * 2;

    Wp[tid * 2] = wpr[tid * 2]; Wp[tid * 2 + 1] = wpr[tid * 2 + 1];
    Bb[tid] = b1[tid];
    if (tid < 128) { msum[tid * 2] = 0.f; msum[tid * 2 + 1] = 0.f; }

#pragma unroll
    for (int it = 0; it < 16; it++) {
        int lin = tid + it * 256;
        int r = lin >> 5;
        int c = (lin & 31) * 2;
        int gr = row0 + r;
        float2 v = make_float2(0.f, 0.f);
        if (gr < E_) v = *(const float2*)(A + (size_t)gr * 64 + c);
        __nv_bfloat16 h0 = __float2bfloat16(v.x);
        __nv_bfloat16 l0 = __float2bfloat16(v.x - __bfloat162float(h0));
        __nv_bfloat16 h1 = __float2bfloat16(v.y);
        __nv_bfloat16 l1 = __float2bfloat16(v.y - __bfloat162float(h1));
        *(__nv_bfloat162*)&Ah[r * ASTR_B + c] = __nv_bfloat162(h0, h1);
        *(__nv_bfloat162*)&Al[r * ASTR_B + c] = __nv_bfloat162(l0, l1);
    }

    float m0[8], m1[8];
#pragma unroll
    for (int i = 0; i < 8; i++) { m0[i] = 0.f; m1[i] = 0.f; }

    for (int cc = 0; cc < 4; cc++) {
        __syncthreads();
#pragma unroll
        for (int it = 0; it < 8; it++) {
            int lin = tid + it * 256;
            int n = lin >> 5;
            int k2 = (lin & 31) * 2;
            *(unsigned*)&Wh[n * ASTR_B + k2] =
                *(const unsigned*)(gwh + (size_t)(cc * 64 + n) * 64 + k2);
            *(unsigned*)&Wl[n * ASTR_B + k2] =
                *(const unsigned*)(gwl + (size_t)(cc * 64 + n) * 64 + k2);
        }
        __syncthreads();

        float c[4][2][4];
#pragma unroll
        for (int mt = 0; mt < 4; mt++)
#pragma unroll
            for (int nt = 0; nt < 2; nt++)
#pragma unroll
                for (int f = 0; f < 4; f++) c[mt][nt][f] = 0.f;

#pragma unroll
        for (int ks = 0; ks < 4; ks++) {
            unsigned bh4[4], bl4[4];
            ldsm_x4(bh4, wh_base + ks * 32);
            ldsm_x4(bl4, wl_base + ks * 32);
#pragma unroll
            for (int mt = 0; mt < 4; mt++) {
                unsigned ah[4], al[4];
                ldsm_x4(ah, ah_base + mt * (16 * ASTR_B * 2) + ks * 32);
                ldsm_x4(al, al_base + mt * (16 * ASTR_B * 2) + ks * 32);
#pragma unroll
                for (int nt = 0; nt < 2; nt++) {
                    unsigned bh[2] = { bh4[nt], bh4[nt + 2] };
                    unsigned bl[2] = { bl4[nt], bl4[nt + 2] };
                    mma_bf16(c[mt][nt], ah, bh);
                    mma_bf16(c[mt][nt], ah, bl);
                    mma_bf16(c[mt][nt], al, bh);
                }
            }
        }

#pragma unroll
        for (int mt = 0; mt < 4; mt++)
#pragma unroll
            for (int nt = 0; nt < 2; nt++)
#pragma unroll
                for (int f = 0; f < 4; f++) {
                    int col = cc * 64 + n0w + nt * 8 + (lane & 3) * 2 + (f & 1);
                    int mi = mt * 2 + (f >> 1);
                    float v = c[mt][nt][f] + Bb[col];
                    v = v > 0.f ? v : (__expf(v) - 1.f);
                    m0[mi] += v * Wp[col * 2];
                    m1[mi] += v * Wp[col * 2 + 1];
                }
    }

#pragma unroll
    for (int i = 0; i < 8; i++) {
        m0[i] += __shfl_xor_sync(0xffffffffu, m0[i], 1);
        m0[i] += __shfl_xor_sync(0xffffffffu, m0[i], 2);
        m1[i] += __shfl_xor_sync(0xffffffffu, m1[i], 1);
        m1[i] += __shfl_xor_sync(0xffffffffu, m1[i], 2);
    }
    if ((lane & 3) == 0) {
#pragma unroll
        for (int i = 0; i < 8; i++) {
            int r = m0w + (i >> 1) * 16 + (lane >> 2) + (i & 1) * 8;
            atomicAdd(&msum[r * 2],     m0[i]);
            atomicAdd(&msum[r * 2 + 1], m1[i]);
        }
    }
    __syncthreads();
    if (tid < 128) {
        int gr = row0 + tid;
        if (gr < E_) {
            int dn = __ldg(&dst[gr]);
            atomicAdd(&msg[2 * dn],     msum[tid * 2]     + cpr[0]);
            atomicAdd(&msg[2 * dn + 1], msum[tid * 2 + 1] + cpr[1]);
        }
    }
}

// ---------------- fused GATv2 (branch-free online segment softmax); dual set via blockIdx.y ----------------
template<int HC>
__global__ __launch_bounds__(256) void k_gat(
    const float* __restrict__ xlr0, const float* __restrict__ att0,
    const float* __restrict__ bias0, float* __restrict__ out0,
    const float* __restrict__ xlr1, const float* __restrict__ att1,
    const float* __restrict__ bias1, float* __restrict__ out1,
    const int* __restrict__ rowptr, const int* __restrict__ csrs,
    int R, int elu)
{
    const float* xlr  = blockIdx.y ? xlr1  : xlr0;
    const float* att  = blockIdx.y ? att1  : att0;
    const float* bias = blockIdx.y ? bias1 : bias0;
    float* out        = blockIdx.y ? out1  : out0;

    constexpr int VEC = HC / 32;
    constexpr int GROUP = 64 / VEC;
    int wid = (int)((blockIdx.x * blockDim.x + threadIdx.x) >> 5);
    int lane = threadIdx.x & 31;
    if (wid >= R) return;

    const float* base = xlr + (size_t)wid * (2 * HC);
    int ch0 = lane * VEC;
    float xl[VEC], xr[VEC], at[VEC], acc[VEC];
    loadv<VEC>(base + ch0, xl);
    loadv<VEC>(base + HC + ch0, xr);
    loadv<VEC>(att + ch0, at);

    float p = 0.f;
#pragma unroll
    for (int i = 0; i < VEC; i++) {
        float v = xl[i] + xr[i];
        v = v > 0.f ? v : 0.2f * v;
        p += at[i] * v;
    }
#pragma unroll
    for (int off = GROUP / 2; off > 0; off >>= 1)
        p += __shfl_xor_sync(0xffffffffu, p, off);

    float m = p, z = 1.f;
#pragma unroll
    for (int i = 0; i < VEC; i++) acc[i] = xl[i];

    int s0 = rowptr[wid], s1 = rowptr[wid + 1];
    for (int q = s0; q < s1; q++) {
        int sv = __ldg(&csrs[q]);
        float xs[VEC];
        loadv<VEC>(xlr + (size_t)sv * (2 * HC) + ch0, xs);
        float pe = 0.f;
#pragma unroll
        for (int i = 0; i < VEC; i++) {
            float v = xs[i] + xr[i];
            v = v > 0.f ? v : 0.2f * v;
            pe += at[i] * v;
        }
#pragma unroll
        for (int off = GROUP / 2; off > 0; off >>= 1)
            pe += __shfl_xor_sync(0xffffffffu, pe, off);

        // branch-free online softmax update (identical values: exp(0)=1, x*1=x)
        float newm = fmaxf(m, pe);
        float sc = __expf(m - newm);
        float wgt = __expf(pe - newm);
        z = z * sc + wgt;
#pragma unroll
        for (int i = 0; i < VEC; i++) acc[i] = acc[i] * sc + wgt * xs[i];
        m = newm;
    }
    float inv = 1.f / z;
    float bv[VEC], o[VEC];
    loadv<VEC>(bias + ch0, bv);
#pragma unroll
    for (int i = 0; i < VEC; i++) {
        float v = acc[i] * inv + bv[i];
        if (elu) v = v > 0.f ? v : (__expf(v) - 1.f);
        o[i] = v;
    }
    storev<VEC>(out + (size_t)wid * HC + ch0, o);
}

// ---------------- gat e2 with fused msg projection (HC=64, H=1) ----------------
__global__ __launch_bounds__(256) void k_gat_msg(
    const float* __restrict__ xlr, const float* __restrict__ att,
    const float* __restrict__ bias, const float* __restrict__ wp,
    const int* __restrict__ rowptr, const int* __restrict__ csrs,
    const int* __restrict__ dst, float* __restrict__ msg)
{
    int wid = (int)((blockIdx.x * blockDim.x + threadIdx.x) >> 5);
    int lane = threadIdx.x & 31;
    if (wid >= N_) return;

    const float* base = xlr + (size_t)wid * 128;
    int ch0 = lane * 2;
    float xl[2], xr[2], at[2], acc[2];
    loadv<2>(base + ch0, xl);
    loadv<2>(base + 64 + ch0, xr);
    loadv<2>(att + ch0, at);

    float p = 0.f;
#pragma unroll
    for (int i = 0; i < 2; i++) {
        float v = xl[i] + xr[i];
        v = v > 0.f ? v : 0.2f * v;
        p += at[i] * v;
    }
#pragma unroll
    for (int off = 16; off > 0; off >>= 1)
        p += __shfl_xor_sync(0xffffffffu, p, off);

    float m = p, z = 1.f;
    acc[0] = xl[0]; acc[1] = xl[1];

    int s0 = rowptr[wid], s1 = rowptr[wid + 1];
    for (int q = s0; q < s1; q++) {
        int sv = __ldg(&csrs[q]);
        float xs[2];
        loadv<2>(xlr + (size_t)sv * 128 + ch0, xs);
        float pe = 0.f;
#pragma unroll
        for (int i = 0; i < 2; i++) {
            float v = xs[i] + xr[i];
            v = v > 0.f ? v : 0.2f * v;
            pe += at[i] * v;
        }
#pragma unroll
        for (int off = 16; off > 0; off >>= 1)
            pe += __shfl_xor_sync(0xffffffffu, pe, off);

        float newm = fmaxf(m, pe);
        float sc = __expf(m - newm);
        float wgt = __expf(pe - newm);
        z = z * sc + wgt;
        acc[0] = acc[0] * sc + wgt * xs[0];
        acc[1] = acc[1] * sc + wgt * xs[1];
        m = newm;
    }
    float inv = 1.f / z;
    float o0 = acc[0] * inv + bias[ch0];
    float o1 = acc[1] * inv + bias[ch0 + 1];
    float pm0 = o0 * wp[ch0 * 2]     + o1 * wp[(ch0 + 1) * 2];
    float pm1 = o0 * wp[ch0 * 2 + 1] + o1 * wp[(ch0 + 1) * 2 + 1];
#pragma unroll
    for (int off = 16; off > 0; off >>= 1) {
        pm0 += __shfl_xor_sync(0xffffffffu, pm0, off);
        pm1 += __shfl_xor_sync(0xffffffffu, pm1, off);
    }
    if (lane == 0) {
        int dn = __ldg(&dst[wid]);
        atomicAdd(&msg[2 * dn],     pm0);
        atomicAdd(&msg[2 * dn + 1], pm1);
    }
}

// ---------------- CRF + proxy heads ----------------
__global__ __launch_bounds__(256) void k_head(
    const float* __restrict__ nr, const float* __restrict__ msg,
    const float* __restrict__ wu, const float* __restrict__ bu,
    const float* __restrict__ w1, const float* __restrict__ b1,
    const float* __restrict__ w2, const float* __restrict__ b2,
    float* __restrict__ out)
{
    __shared__ float s_w1[64 * 128];
    __shared__ float s_w2[128 * 2];
    __shared__ float s_wu[128];
    int tid = threadIdx.x;
    for (int i = tid; i < 64 * 128; i += 256) s_w1[i] = w1[i];
    if (tid < 256) s_w2[tid] = w2[tid];
    if (tid < 128) s_wu[tid] = wu[tid];
    __syncthreads();

    int wid = (int)((blockIdx.x * blockDim.x + tid) >> 5);
    int lane = tid & 31;
    if (wid >= N_) return;

    int k0 = lane * 2;
    float2 xp = *(const float2*)(nr + (size_t)wid * 64 + k0);
    float x0 = xp.x, x1 = xp.y;

    float u0 = x0 * s_wu[k0 * 2]     + x1 * s_wu[(k0 + 1) * 2];
    float u1 = x0 * s_wu[k0 * 2 + 1] + x1 * s_wu[(k0 + 1) * 2 + 1];
#pragma unroll
    for (int off = 16; off > 0; off >>= 1) {
        u0 += __shfl_xor_sync(0xffffffffu, u0, off);
        u1 += __shfl_xor_sync(0xffffffffu, u1, off);
    }
    float v0 = u0 + bu[0] + msg[2 * wid];
    float v1 = u1 + bu[1] + msg[2 * wid + 1];
    float mx = fmaxf(v0, v1);
    float l = logf(__expf(v0 - mx) + __expf(v1 - mx));

    int c0 = lane * 4;
    float ph[4];
#pragma unroll
    for (int jj = 0; jj < 4; jj++) ph[jj] = b1[c0 + jj];
    for (int k = 0; k < 64; k++) {
        float xk = __shfl_sync(0xffffffffu, (k & 1) ? x1 : x0, k >> 1);
#pragma unroll
        for (int jj = 0; jj < 4; jj++) ph[jj] += xk * s_w1[k * 128 + c0 + jj];
    }
    float p0 = 0.f, p1 = 0.f;
#pragma unroll
    for (int jj = 0; jj < 4; jj++) {
        float r = ph[jj] > 0.f ? ph[jj] : 0.f;
        p0 += r * s_w2[(c0 + jj) * 2];
        p1 += r * s_w2[(c0 + jj) * 2 + 1];
    }
#pragma unroll
    for (int off = 16; off > 0; off >>= 1) {
        p0 += __shfl_xor_sync(0xffffffffu, p0, off);
        p1 += __shfl_xor_sync(0xffffffffu, p1, off);
    }
    if (lane == 0) {
        out[(size_t)wid * 2]     = v0 - mx - l;
        out[(size_t)wid * 2 + 1] = v1 - mx - l;
        out[(size_t)2 * N_ + wid * 2]     = p0 + b2[0];
        out[(size_t)2 * N_ + wid * 2 + 1] = p1 + b2[1];
    }
}

// ---------------- launch ----------------
extern "C" void kernel_launch(void* const* d_in, const int* in_sizes, int n_in,
                              void* d_out, int out_size)
{
    const float* x         = (const float*)d_in[0];
    const float* edge_type = (const float*)d_in[1];
    const int*   ei        = (const int*)  d_in[2];
    const float* n1_wl = (const float*)d_in[3];
    const float* n1_wr = (const float*)d_in[4];
    const float* n1_att= (const float*)d_in[5];
    const float* n1_b  = (const float*)d_in[6];
    const float* n2_wl = (const float*)d_in[7];
    const float* n2_wr = (const float*)d_in[8];
    const float* n2_att= (const float*)d_in[9];
    const float* n2_b  = (const float*)d_in[10];
    const float* e1_wl = (const float*)d_in[11];
    const float* e1_wr = (const float*)d_in[12];
    const float* e1_att= (const float*)d_in[13];
    const float* e1_b  = (const float*)d_in[14];
    const float* e2_wl = (const float*)d_in[15];
    const float* e2_wr = (const float*)d_in[16];
    const float* e2_att= (const float*)d_in[17];
    const float* e2_b  = (const float*)d_in[18];
    const float* crf_wu= (const float*)d_in[19];
    const float* crf_bu= (const float*)d_in[20];
    const float* crf_wp= (const float*)d_in[21];
    const float* px_w1 = (const float*)d_in[22];
    const float* px_b1 = (const float*)d_in[23];
    const float* px_w2 = (const float*)d_in[24];
    const float* px_b2 = (const float*)d_in[25];

    const int* src = ei;
    const int* dst = ei + E_;

    float *xlr_n1, *h, *xlr_n2, *nr, *xlr_e1, *g, *xlr_e2, *msg, *wpr, *cpr;
    __nv_bfloat16 *n1h, *n1l, *n2h, *n2l, *e1h, *e1l, *e2h, *e2l;
    int *cnt, *rowptr, *headp, *csrs;
    cudaGetSymbolAddress((void**)&xlr_n1, d_xlr_n1);
    cudaGetSymbolAddress((void**)&h,      d_h);
    cudaGetSymbolAddress((void**)&xlr_n2, d_xlr_n2);
    cudaGetSymbolAddress((void**)&nr,     d_nr);
    cudaGetSymbolAddress((void**)&xlr_e1, d_xlr_e1);
    cudaGetSymbolAddress((void**)&g,      d_g);
    cudaGetSymbolAddress((void**)&xlr_e2, d_xlr_e2);
    cudaGetSymbolAddress((void**)&msg,    d_msg);
    cudaGetSymbolAddress((void**)&wpr,    d_wpr);
    cudaGetSymbolAddress((void**)&cpr,    d_cpr);
    cudaGetSymbolAddress((void**)&n1h,    d_n1h);
    cudaGetSymbolAddress((void**)&n1l,    d_n1l);
    cudaGetSymbolAddress((void**)&n2h,    d_n2h);
    cudaGetSymbolAddress((void**)&n2l,    d_n2l);
    cudaGetSymbolAddress((void**)&e1h,    d_e1h);
    cudaGetSymbolAddress((void**)&e1l,    d_e1l);
    cudaGetSymbolAddress((void**)&e2h,    d_e2h);
    cudaGetSymbolAddress((void**)&e2l,    d_e2l);
    cudaGetSymbolAddress((void**)&cnt,    d_cnt);
    cudaGetSymbolAddress((void**)&rowptr, d_rowptr);
    cudaGetSymbolAddress((void**)&headp,  d_headp);
    cudaGetSymbolAddress((void**)&csrs,   d_csrs);

    cudaFuncSetAttribute(k_fused, cudaFuncAttributeMaxDynamicSharedMemorySize,
                         FUSED_SMEM_B);
    cudaFuncSetAttribute(k_gemmt, cudaFuncAttributeMaxDynamicSharedMemorySize,
                         GEMMT_SMEM);

    const int GB_N = (N_ + 127) / 128;             // 157
    const int GW_N = (N_ + 7) / 8;                 // 2500
    const int FUSED_BLKS = (E_ - N_ + 127) / 128;  // 2344

    ensure_resources();
    const bool forked = (g_s1 != 0 && g_s2 != 0);

    // ---- merged prolog ----
    k_prolog<<<512 + 157 + 1, 256>>>(n1_wl, n1_wr, n2_wl, n2_wr,
                                     e1_wl, e1_wr, e2_wl, e2_wr,
                                     crf_wp, e2_b,
                                     n1h, n1l, n2h, n2l, e1h, e1l, e2h, e2l,
                                     wpr, cpr, msg, cnt);

    if (forked) {
        cudaEventRecord(g_evA, 0);
        cudaStreamWaitEvent(g_s1, g_evA, 0);
        cudaStreamWaitEvent(g_s2, g_evA, 0);

        // s2: BOTH layer-1 GEMMs (node + edge) in one launch — critical chain first
        k_gemmt<<<dim3(GB_N, 8, 2), 256, GEMMT_SMEM, g_s2>>>(
            x, n1h, n1l, xlr_n1, edge_type, e1h, e1l, xlr_e1, N_, 64, 512);

        // s1: fused empty-row edge path
        k_fused<<<FUSED_BLKS, 256, FUSED_SMEM_B, g_s1>>>(edge_type, e1_b, wpr, cpr,
                                                         e1h, e1l, dst, msg);
        cudaEventRecord(g_evF, g_s1);

        // s0: CSR build (concurrent with gemmt + fused)
        k_hist   <<<(E_ + 255) / 256, 256>>>(dst, cnt);
        k_scan   <<<1, 1024>>>(cnt, rowptr, headp);
        k_scatter<<<(E_ + 255) / 256, 256>>>(src, dst, headp, csrs);
        cudaEventRecord(g_evCSR, 0);
        cudaStreamWaitEvent(g_s2, g_evCSR, 0);

        // s2: BOTH gat<256> (node h, edge g)
        k_gat<256><<<dim3(GW_N, 2), 256, 0, g_s2>>>(
            xlr_n1, n1_att, n1_b, h, xlr_e1, e1_att, e1_b, g,
            rowptr, csrs, N_, 1);
        // s2: BOTH layer-2 GEMMs
        k_gemmt<<<dim3(GB_N, 2, 2), 256, GEMMT_SMEM, g_s2>>>(
            h, n2h, n2l, xlr_n2, g, e2h, e2l, xlr_e2, N_, 256, 128);
        cudaEventRecord(g_evS, g_s2);
        cudaStreamWaitEvent(0, g_evS, 0);

        // s2: node gat<64> -> nr;  s0: edge gat_msg -> msg (independent)
        k_gat<64><<<dim3(GW_N, 1), 256, 0, g_s2>>>(
            xlr_n2, n2_att, n2_b, nr, xlr_n2, n2_att, n2_b, nr,
            rowptr, csrs, N_, 0);
        cudaEventRecord(g_evN, g_s2);
        k_gat_msg<<<GW_N, 256>>>(xlr_e2, e2_att, e2_b, crf_wp, rowptr, csrs, dst, msg);

        // join + heads
        cudaStreamWaitEvent(0, g_evF, 0);
        cudaStreamWaitEvent(0, g_evN, 0);
        k_head<<<GW_N, 256>>>(nr, msg, crf_wu, crf_bu, px_w1, px_b1, px_w2, px_b2,
                              (float*)d_out);
    } else {
        // serial fallback (same work, single stream)
        k_fused<<<FUSED_BLKS, 256, FUSED_SMEM_B>>>(edge_type, e1_b, wpr, cpr,
                                                   e1h, e1l, dst, msg);

        k_hist   <<<(E_ + 255) / 256, 256>>>(dst, cnt);
        k_scan   <<<1, 1024>>>(cnt, rowptr, headp);
        k_scatter<<<(E_ + 255) / 256, 256>>>(src, dst, headp, csrs);

        k_gemmt<<<dim3(GB_N, 8, 2), 256, GEMMT_SMEM>>>(
            x, n1h, n1l, xlr_n1, edge_type, e1h, e1l, xlr_e1, N_, 64, 512);
        k_gat<256><<<dim3(GW_N, 2), 256>>>(
            xlr_n1, n1_att, n1_b, h, xlr_e1, e1_att, e1_b, g,
            rowptr, csrs, N_, 1);
        k_gemmt<<<dim3(GB_N, 2, 2), 256, GEMMT_SMEM>>>(
            h, n2h, n2l, xlr_n2, g, e2h, e2l, xlr_e2, N_, 256, 128);
        k_gat<64><<<dim3(GW_N, 1), 256>>>(
            xlr_n2, n2_att, n2_b, nr, xlr_n2, n2_att, n2_b, nr,
            rowptr, csrs, N_, 0);
        k_gat_msg<<<GW_N, 256>>>(xlr_e2, e2_att, e2_b, crf_wp, rowptr, csrs, dst, msg);

        k_head<<<GW_N, 256>>>(nr, msg, crf_wu, crf_bu, px_w1, px_b1, px_w2, px_b2,
                              (float*)d_out);
    }
}